// round 1
// baseline (speedup 1.0000x reference)
#include <cuda_runtime.h>
#include <float.h>

// Problem constants
#define B_   4
#define N_   4096
#define K_   16

// Scratch (allocation-free rule: __device__ globals)
__device__ int   g_knn_idx[B_ * N_ * K_];
__device__ float g_basis[B_ * N_ * K_ * 20];

// ---------------------------------------------------------------------------
// KNN + Taylor basis.
// One thread per query point. Candidates tiled through shared memory.
// d2 computed exactly like the reference: sq_i + sq_j - 2*dot, with forced
// rounding so self-distance is exactly 0 and ties keep ascending index
// (matches jax.lax.top_k stable ordering).
// ---------------------------------------------------------------------------
__global__ void knn_basis_kernel(const float* __restrict__ pc)
{
    const int b = blockIdx.y;
    const int n = blockIdx.x * 128 + threadIdx.x;
    const float* pcb = pc + (size_t)b * N_ * 6;

    const float qx = pcb[n * 6 + 0];
    const float qy = pcb[n * 6 + 1];
    const float qz = pcb[n * 6 + 2];
    const float qsq = __fadd_rn(__fadd_rn(__fmul_rn(qx, qx), __fmul_rn(qy, qy)),
                                __fmul_rn(qz, qz));

    float dist[K_];
    int   nid[K_];
#pragma unroll
    for (int i = 0; i < K_; i++) { dist[i] = FLT_MAX; nid[i] = 0; }

    __shared__ float4 s_c[1024];

    for (int tile = 0; tile < N_; tile += 1024) {
        __syncthreads();
        for (int i = threadIdx.x; i < 1024; i += 128) {
            int j = tile + i;
            float x = pcb[j * 6 + 0];
            float y = pcb[j * 6 + 1];
            float z = pcb[j * 6 + 2];
            float sq = __fadd_rn(__fadd_rn(__fmul_rn(x, x), __fmul_rn(y, y)),
                                 __fmul_rn(z, z));
            s_c[i] = make_float4(x, y, z, sq);
        }
        __syncthreads();

        for (int i = 0; i < 1024; i++) {
            float4 c = s_c[i];
            float dot = __fadd_rn(__fadd_rn(__fmul_rn(qx, c.x), __fmul_rn(qy, c.y)),
                                  __fmul_rn(qz, c.z));
            float d2 = __fsub_rn(__fadd_rn(qsq, c.w), __fmul_rn(2.0f, dot));
            if (d2 < dist[K_ - 1]) {
                dist[K_ - 1] = d2;
                nid[K_ - 1] = tile + i;
#pragma unroll
                for (int j = K_ - 1; j > 0; --j) {
                    if (dist[j] < dist[j - 1]) {
                        float td = dist[j]; dist[j] = dist[j - 1]; dist[j - 1] = td;
                        int ti = nid[j]; nid[j] = nid[j - 1]; nid[j - 1] = ti;
                    }
                }
            }
        }
    }

    int*   iout = g_knn_idx + ((size_t)b * N_ + n) * K_;
    float* bout = g_basis + (((size_t)b * N_ + n) * K_) * 20;
#pragma unroll
    for (int k = 0; k < K_; k++) {
        int j = nid[k];
        iout[k] = j;
        float x = pcb[j * 6 + 0] - qx;
        float y = pcb[j * 6 + 1] - qy;
        float z = pcb[j * 6 + 2] - qz;
        float* o = bout + k * 20;
        o[0] = 1.0f; o[1] = x; o[2] = y; o[3] = z;
        o[4] = x * x; o[5] = x * y; o[6] = x * z;
        o[7] = y * y; o[8] = y * z; o[9] = z * z;
        o[10] = x * x * x; o[11] = x * x * y; o[12] = x * x * z;
        o[13] = x * y * y; o[14] = x * y * z; o[15] = x * z * z;
        o[16] = y * y * y; o[17] = y * y * z; o[18] = y * z * z;
        o[19] = z * z * z;
    }
}

// ---------------------------------------------------------------------------
// SpiderConv layer: out[b,o,n] = relu( sum_{c,t,k} gf*tay*W + b2 )
// GEMM framing: M=128 points per block, Kdim chunked 48-wide per input
// channel c (t*16+k), N = BN output channels per block.
// E (fused activations) generated on the fly into shared each c-iteration.
// ---------------------------------------------------------------------------
template<int CIN, int COUT, int BN>
__global__ void __launch_bounds__(256, 2)
layer_kernel(const float* __restrict__ feat_in, int strideB, int strideJ, int strideC,
             const float* __restrict__ w1, const float* __restrict__ b1,
             const float* __restrict__ w2, const float* __restrict__ b2,
             float* __restrict__ pf_out)   // base at this layer's channel 0
{
    constexpr int TN = BN / 16;

    extern __shared__ float smem[];
    float* s_tay = smem;                 // [48][128]
    float* s_E   = s_tay + 48 * 128;     // [48][128]
    float* s_W   = s_E + 48 * 128;       // [BN][49] (padded)
    float* s_w1  = s_W + BN * 49;        // 60 w1 + 3 b1

    const int tid = threadIdx.x;
    const int bp  = blockIdx.x;
    const int b   = bp >> 5;             // 32 point-blocks per batch
    const int n0  = (bp & 31) * 128;
    const int ob  = blockIdx.y * BN;

    if (tid < 60) s_w1[tid] = w1[tid];
    if (tid < 3)  s_w1[60 + tid] = b1[tid];

    // per-thread fixed (p,k) assignment; neighbor offsets kept in registers
    int joff[8];
    const float* fb = feat_in + (size_t)b * strideB;
#pragma unroll
    for (int r = 0; r < 8; r++) {
        int pid = tid + r * 256;
        int p = pid & 127, k = pid >> 7;
        int j = g_knn_idx[(((size_t)b * N_ + n0 + p) << 4) + k];
        joff[r] = j * strideJ;
    }
    __syncthreads();

    // stage tay[t*16+k][p] = b1[t] + sum_j basis[j]*w1[t][j]
#pragma unroll
    for (int r = 0; r < 8; r++) {
        int pid = tid + r * 256;
        int p = pid & 127, k = pid >> 7;
        const float* bas = g_basis + ((((size_t)b * N_ + n0 + p) << 4) + k) * 20;
        float t0 = s_w1[60], t1 = s_w1[61], t2 = s_w1[62];
#pragma unroll
        for (int j = 0; j < 20; j++) {
            float v = bas[j];
            t0 += v * s_w1[j];
            t1 += v * s_w1[20 + j];
            t2 += v * s_w1[40 + j];
        }
        s_tay[(0 * 16 + k) * 128 + p] = t0;
        s_tay[(1 * 16 + k) * 128 + p] = t1;
        s_tay[(2 * 16 + k) * 128 + p] = t2;
    }

    float acc[8][TN];
#pragma unroll
    for (int i = 0; i < 8; i++)
#pragma unroll
        for (int j = 0; j < TN; j++) acc[i][j] = 0.0f;

    const int tx = tid & 15;
    const int ty = tid >> 4;

    for (int c = 0; c < CIN; c++) {
        __syncthreads();

        // stage W chunk: s_W[o][t*16+k] = w2[(ob+o)*CIN*48 + c*48 + tkk]
        const float* w2c = w2 + (size_t)ob * (CIN * 48) + c * 48;
#pragma unroll 4
        for (int i = tid; i < BN * 48; i += 256) {
            int o = i / 48, tkk = i % 48;
            s_W[o * 49 + tkk] = w2c[(size_t)o * (CIN * 48) + tkk];
        }

        // stage E: gather gf and fuse with tay
#pragma unroll
        for (int r = 0; r < 8; r++) {
            int pid = tid + r * 256;
            int p = pid & 127, k = pid >> 7;
            float g = fb[joff[r] + c * strideC];
            s_E[(0 * 16 + k) * 128 + p] = g * s_tay[(0 * 16 + k) * 128 + p];
            s_E[(1 * 16 + k) * 128 + p] = g * s_tay[(1 * 16 + k) * 128 + p];
            s_E[(2 * 16 + k) * 128 + p] = g * s_tay[(2 * 16 + k) * 128 + p];
        }
        __syncthreads();

        // GEMM: acc[8][TN] += E[kk][p] * W[o][kk]
#pragma unroll
        for (int kk = 0; kk < 48; kk++) {
            float a[8];
            float4 a0 = *reinterpret_cast<const float4*>(&s_E[kk * 128 + ty * 8]);
            float4 a1 = *reinterpret_cast<const float4*>(&s_E[kk * 128 + ty * 8 + 4]);
            a[0] = a0.x; a[1] = a0.y; a[2] = a0.z; a[3] = a0.w;
            a[4] = a1.x; a[5] = a1.y; a[6] = a1.z; a[7] = a1.w;
            float bb[TN];
#pragma unroll
            for (int j = 0; j < TN; j++) bb[j] = s_W[(tx * TN + j) * 49 + kk];
#pragma unroll
            for (int i = 0; i < 8; i++)
#pragma unroll
                for (int j = 0; j < TN; j++)
                    acc[i][j] = fmaf(a[i], bb[j], acc[i][j]);
        }
    }

    // epilogue: bias + relu, store channel-major into point_feat region
#pragma unroll
    for (int j = 0; j < TN; j++) {
        int o = ob + tx * TN + j;
        float bias = b2[o];
        float* col = pf_out + ((size_t)b * 480 + o) * N_ + n0 + ty * 8;
        float4 v0, v1;
        v0.x = fmaxf(acc[0][j] + bias, 0.0f);
        v0.y = fmaxf(acc[1][j] + bias, 0.0f);
        v0.z = fmaxf(acc[2][j] + bias, 0.0f);
        v0.w = fmaxf(acc[3][j] + bias, 0.0f);
        v1.x = fmaxf(acc[4][j] + bias, 0.0f);
        v1.y = fmaxf(acc[5][j] + bias, 0.0f);
        v1.z = fmaxf(acc[6][j] + bias, 0.0f);
        v1.w = fmaxf(acc[7][j] + bias, 0.0f);
        reinterpret_cast<float4*>(col)[0] = v0;
        reinterpret_cast<float4*>(col)[1] = v1;
    }
}

// ---------------------------------------------------------------------------
// top-2 over N per (b, channel) row; one warp per row.
// ---------------------------------------------------------------------------
__global__ void top2_kernel(const float* __restrict__ pf, float* __restrict__ cat)
{
    int row  = blockIdx.x * 4 + (threadIdx.x >> 5);
    int lane = threadIdx.x & 31;
    if (row >= B_ * 480) return;

    const float* p = pf + (size_t)row * N_;
    float m1 = -FLT_MAX, m2 = -FLT_MAX;
    for (int i = lane; i < N_; i += 32) {
        float v = p[i];
        if (v > m1) { m2 = m1; m1 = v; }
        else if (v > m2) { m2 = v; }
    }
#pragma unroll
    for (int off = 16; off; off >>= 1) {
        float o1 = __shfl_down_sync(0xFFFFFFFFu, m1, off);
        float o2 = __shfl_down_sync(0xFFFFFFFFu, m2, off);
        float nm1 = fmaxf(m1, o1);
        float nm2 = fmaxf(fminf(m1, o1), fmaxf(m2, o2));
        m1 = nm1; m2 = nm2;
    }
    if (lane == 0) {
        int b = row / 480, ch = row % 480;
        cat[(size_t)b * 960 + ch * 2 + 0] = m1;
        cat[(size_t)b * 960 + ch * 2 + 1] = m2;
    }
}

// ---------------------------------------------------------------------------
// launch
// ---------------------------------------------------------------------------
static inline size_t layer_smem(int BN)
{
    return (size_t)(48 * 128 * 2 + BN * 49 + 64) * sizeof(float);
}

extern "C" void kernel_launch(void* const* d_in, const int* in_sizes, int n_in,
                              void* d_out, int out_size)
{
    (void)in_sizes; (void)n_in; (void)out_size;

    const float* pc   = (const float*)d_in[0];
    const float* w1_1 = (const float*)d_in[1];
    const float* b1_1 = (const float*)d_in[2];
    const float* w2_1 = (const float*)d_in[3];
    const float* b2_1 = (const float*)d_in[4];
    const float* w1_2 = (const float*)d_in[5];
    const float* b1_2 = (const float*)d_in[6];
    const float* w2_2 = (const float*)d_in[7];
    const float* b2_2 = (const float*)d_in[8];
    const float* w1_3 = (const float*)d_in[9];
    const float* b1_3 = (const float*)d_in[10];
    const float* w2_3 = (const float*)d_in[11];
    const float* b2_3 = (const float*)d_in[12];
    const float* w1_4 = (const float*)d_in[13];
    const float* b1_4 = (const float*)d_in[14];
    const float* w2_4 = (const float*)d_in[15];
    const float* b2_4 = (const float*)d_in[16];

    float* out = (float*)d_out;
    float* cat = out;               // (B, 960)
    float* pf  = out + B_ * 960;    // (B, 480, N) channel-major

    // opt-in to >48KB dynamic shared (idempotent, non-stream API)
    cudaFuncSetAttribute(layer_kernel<6, 32, 32>,
                         cudaFuncAttributeMaxDynamicSharedMemorySize, (int)layer_smem(32));
    cudaFuncSetAttribute(layer_kernel<32, 64, 64>,
                         cudaFuncAttributeMaxDynamicSharedMemorySize, (int)layer_smem(64));
    cudaFuncSetAttribute(layer_kernel<64, 128, 128>,
                         cudaFuncAttributeMaxDynamicSharedMemorySize, (int)layer_smem(128));
    cudaFuncSetAttribute(layer_kernel<128, 256, 128>,
                         cudaFuncAttributeMaxDynamicSharedMemorySize, (int)layer_smem(128));

    knn_basis_kernel<<<dim3(N_ / 128, B_), 128>>>(pc);

    // Layer 1: input = pc (B,N,6) point-major; output channels [0,32)
    layer_kernel<6, 32, 32><<<dim3(128, 1), 256, layer_smem(32)>>>(
        pc, N_ * 6, 6, 1, w1_1, b1_1, w2_1, b2_1, pf + (size_t)0 * N_);

    // Layer 2: input channels [0,32); output [32,96)
    layer_kernel<32, 64, 64><<<dim3(128, 1), 256, layer_smem(64)>>>(
        pf, 480 * N_, 1, N_, w1_2, b1_2, w2_2, b2_2, pf + (size_t)32 * N_);

    // Layer 3: input [32,96); output [96,224)
    layer_kernel<64, 128, 128><<<dim3(128, 1), 256, layer_smem(128)>>>(
        pf + (size_t)32 * N_, 480 * N_, 1, N_, w1_3, b1_3, w2_3, b2_3,
        pf + (size_t)96 * N_);

    // Layer 4: input [96,224); output [224,480)
    layer_kernel<128, 256, 128><<<dim3(128, 2), 256, layer_smem(128)>>>(
        pf + (size_t)96 * N_, 480 * N_, 1, N_, w1_4, b1_4, w2_4, b2_4,
        pf + (size_t)224 * N_);

    top2_kernel<<<(B_ * 480) / 4, 128>>>(pf, cat);
}